// round 14
// baseline (speedup 1.0000x reference)
#include <cuda_runtime.h>
#include <cstdint>
#include <math.h>

#define K_DIM 1024
#define N_EXPERTS 64
#define BM 128
#define KCHUNK 16
#define NCHUNK 64
#define GTOK 64                    // tokens per group
// FFMA group region: mainloop xs[16][68]+ws[16][68]=2176 fl; epilogue lg[64][68]=4352
#define F_REGION 4352
#define F_K_STRIDE 68
// MMA group region: xs[64][36]+ws[64][36]=4608 fl; epilogue lg[64][68]=4352
#define M_REGION 4608
#define M_STRIDE 36
#define LG_STRIDE 68
#define SMEM_FLOATS (F_REGION + M_REGION)   // 8960 -> 35840 B
#define TH 7e-3f
#define FULL 0xffffffffu

#define GBAR(id) asm volatile("bar.sync %0, 128;" :: "r"(id) : "memory")

#define MMA_TF32(d, a, b) \
    asm volatile("mma.sync.aligned.m16n8k8.row.col.f32.tf32.tf32.f32 " \
        "{%0,%1,%2,%3}, {%4,%5,%6,%7}, {%8,%9}, {%0,%1,%2,%3};" \
        : "+f"((d)[0]), "+f"((d)[1]), "+f"((d)[2]), "+f"((d)[3]) \
        : "r"((a)[0]), "r"((a)[1]), "r"((a)[2]), "r"((a)[3]), "r"((b)[0]), "r"((b)[1]))

#define INS4(vv, ii) do {                                                     \
    const float _v = (vv); const int _i = (ii);                               \
    if (_v > t3) {                                                            \
        if (_v > t2) { t3 = t2; j3 = j2;                                      \
            if (_v > t1) { t2 = t1; j2 = j1;                                  \
                if (_v > t0) { t1 = t0; j1 = j0; t0 = _v; j0 = _i; }          \
                else         { t1 = _v; j1 = _i; } }                          \
            else { t2 = _v; j2 = _i; } }                                      \
        else { t3 = _v; j3 = _i; } }                                          \
} while (0)

__global__ __launch_bounds__(256, 2)
void router_dual_kernel(const float* __restrict__ x,
                        const float* __restrict__ Wm,
                        const float* __restrict__ bias,
                        float* __restrict__ out,
                        int num_tokens) {
    extern __shared__ float smem[];
    const int tid  = threadIdx.x;
    const int gid  = tid >> 7;          // 0 = FFMA group, 1 = MMA group
    const int gtid = tid & 127;
    const int lid  = tid & 31;
    const int bm   = blockIdx.x * BM;
    float* oid = out + (size_t)num_tokens * 2;
    const float4* b4 = (const float4*)bias;

    if (gid == 0) {
        // ================= FFMA group: tokens [bm, bm+64), exact fp32 =================
        float* xs = smem;                       // [16][68]
        float* ws = smem + 16 * F_K_STRIDE;     // [16][68]

        const int row = gtid;                   // 0..63 x rows, 64..127 W rows
        const int tym = gtid >> 3;              // 0..15 -> tokens tym*4..+3
        const int txk = gtid & 7;               // 0..7  -> experts txk*8..+7

        float acc[4][8];
        #pragma unroll
        for (int i = 0; i < 4; ++i)
            #pragma unroll
            for (int j = 0; j < 8; ++j) acc[i][j] = 0.0f;

        const float* grow = (row < 64) ? (x + (size_t)(bm + row) * K_DIM)
                                       : (Wm + (size_t)(row - 64) * K_DIM);
        float* dst = (row < 64) ? xs : ws;
        const int col = row & 63;

        #pragma unroll 1
        for (int c = 0; c < NCHUNK; ++c) {
            // load own chunk: 16 k of one row
            float4 v[4];
            #pragma unroll
            for (int j = 0; j < 4; ++j)
                v[j] = __ldg((const float4*)(grow + c * KCHUNK + j * 4));
            #pragma unroll
            for (int j = 0; j < 4; ++j) {
                dst[(j * 4 + 0) * F_K_STRIDE + col] = v[j].x;
                dst[(j * 4 + 1) * F_K_STRIDE + col] = v[j].y;
                dst[(j * 4 + 2) * F_K_STRIDE + col] = v[j].z;
                dst[(j * 4 + 3) * F_K_STRIDE + col] = v[j].w;
            }
            GBAR(1);
            #pragma unroll 4
            for (int k = 0; k < KCHUNK; ++k) {
                const float4 a  = *(const float4*)&xs[k * F_K_STRIDE + tym * 4];
                const float4 b0 = *(const float4*)&ws[k * F_K_STRIDE + txk * 8];
                const float4 b1 = *(const float4*)&ws[k * F_K_STRIDE + txk * 8 + 4];
                const float am[4] = {a.x, a.y, a.z, a.w};
                const float bn[8] = {b0.x, b0.y, b0.z, b0.w, b1.x, b1.y, b1.z, b1.w};
                #pragma unroll
                for (int i = 0; i < 4; ++i)
                    #pragma unroll
                    for (int j = 0; j < 8; ++j)
                        acc[i][j] = fmaf(am[i], bn[j], acc[i][j]);
            }
            GBAR(1);
        }

        // dump logits [64][68] (aliases xs/ws; fenced by the last barrier)
        float* lg = smem;
        #pragma unroll
        for (int i = 0; i < 4; ++i)
            #pragma unroll
            for (int j = 0; j < 8; ++j)
                lg[(tym * 4 + i) * LG_STRIDE + txk * 8 + j] = acc[i][j];
        GBAR(1);
        if (gtid >= GTOK) return;

        // exact per-token epilogue
        const float4* lrow = (const float4*)&lg[gtid * LG_STRIDE];
        float v[64];
        #pragma unroll
        for (int q = 0; q < 16; ++q) {
            const float4 lv = lrow[q];
            const float4 bv = __ldg(b4 + q);
            v[q * 4 + 0] = lv.x + bv.x;
            v[q * 4 + 1] = lv.y + bv.y;
            v[q * 4 + 2] = lv.z + bv.z;
            v[q * 4 + 3] = lv.w + bv.w;
        }
        float m1 = -INFINITY, m2 = -INFINITY;
        int i1 = 0, i2 = 0;
        #pragma unroll
        for (int e = 0; e < 64; ++e) {
            if (v[e] > m1) { m2 = m1; i2 = i1; m1 = v[e]; i1 = e; }
            else if (v[e] > m2) { m2 = v[e]; i2 = e; }
        }
        float s = 0.0f;
        #pragma unroll
        for (int e = 0; e < 64; ++e) s += __expf(v[e] - m1);

        const float inv = 1.0f / s;
        const int tk = bm + gtid;
        *(float2*)&out[tk * 2] = make_float2(inv, __expf(m2 - m1) * inv);
        *(float2*)&oid[tk * 2] = make_float2((float)i1, (float)i2);
        return;
    }

    // ================= MMA group: tokens [bm+64, bm+128), tf32 + exact fixup =================
    {
        float* xs = smem + F_REGION;             // [64][36] tokens
        float* ws = xs + 64 * M_STRIDE;          // [64][36] experts

        const int row  = gtid;                   // 0..63 x rows, 64..127 W rows
        const int mwid = gtid >> 5;              // warp in group 0..3
        const int r  = lid >> 2;
        const int cq = lid & 3;

        float acc[4][2][4];                      // [m-tile experts][n-tile tokens][frag]
        #pragma unroll
        for (int mt = 0; mt < 4; ++mt)
            #pragma unroll
            for (int nt = 0; nt < 2; ++nt)
                #pragma unroll
                for (int q = 0; q < 4; ++q) acc[mt][nt][q] = 0.0f;

        const float* grow = (row < 64) ? (x + (size_t)(bm + 64 + row) * K_DIM)
                                       : (Wm + (size_t)(row - 64) * K_DIM);
        float* dst = ((row < 64) ? xs : ws) + (row & 63) * M_STRIDE;

        #pragma unroll 1
        for (int c = 0; c < NCHUNK; ++c) {
            float4 v[4];
            #pragma unroll
            for (int j = 0; j < 4; ++j)
                v[j] = __ldg((const float4*)(grow + c * KCHUNK + j * 4));
            #pragma unroll
            for (int j = 0; j < 4; ++j)
                *(float4*)&dst[j * 4] = v[j];
            GBAR(2);

            const uint32_t* xsp = (const uint32_t*)xs;
            const uint32_t* wsp = (const uint32_t*)ws;
            #pragma unroll
            for (int ks = 0; ks < 2; ++ks) {
                const int kc = ks * 8 + cq;
                uint32_t bf[2][2], af[4][4];
                #pragma unroll
                for (int nt = 0; nt < 2; ++nt) {
                    const int tr = mwid * 16 + nt * 8 + r;
                    bf[nt][0] = xsp[tr * M_STRIDE + kc];
                    bf[nt][1] = xsp[tr * M_STRIDE + kc + 4];
                }
                #pragma unroll
                for (int mt = 0; mt < 4; ++mt) {
                    const int er = mt * 16 + r;
                    af[mt][0] = wsp[er * M_STRIDE + kc];
                    af[mt][1] = wsp[(er + 8) * M_STRIDE + kc];
                    af[mt][2] = wsp[er * M_STRIDE + kc + 4];
                    af[mt][3] = wsp[(er + 8) * M_STRIDE + kc + 4];
                }
                #pragma unroll
                for (int mt = 0; mt < 4; ++mt)
                    #pragma unroll
                    for (int nt = 0; nt < 2; ++nt)
                        MMA_TF32(acc[mt][nt], af[mt], bf[nt]);
            }
            GBAR(2);
        }

        // dump logits [64][68] at group region base
        float* lg = smem + F_REGION;
        #pragma unroll
        for (int mt = 0; mt < 4; ++mt)
            #pragma unroll
            for (int nt = 0; nt < 2; ++nt)
                #pragma unroll
                for (int q = 0; q < 4; ++q) {
                    const int tr = mwid * 16 + nt * 8 + 2 * cq + (q & 1);
                    const int e  = mt * 16 + r + (q >> 1) * 8;
                    lg[tr * LG_STRIDE + e] = acc[mt][nt][q];
                }
        GBAR(2);
        if (mwid >= 2) return;

        // per-token epilogue with fixup: thread owns local token mwid*32+lid
        const int ltk = mwid * 32 + lid;
        const float4* lrow = (const float4*)&lg[ltk * LG_STRIDE];

        float t0 = -INFINITY, t1 = -INFINITY, t2 = -INFINITY, t3 = -INFINITY;
        int j0 = 0, j1 = 0, j2 = 0, j3 = 0;
        float vv[64];
        #pragma unroll
        for (int q = 0; q < 16; ++q) {
            const float4 lv = lrow[q];
            const float4 bv = __ldg(b4 + q);
            vv[q * 4 + 0] = lv.x + bv.x;
            vv[q * 4 + 1] = lv.y + bv.y;
            vv[q * 4 + 2] = lv.z + bv.z;
            vv[q * 4 + 3] = lv.w + bv.w;
        }
        #pragma unroll
        for (int e = 0; e < 64; ++e) INS4(vv[e], e);

        float s = 0.0f;
        #pragma unroll
        for (int e = 0; e < 64; ++e) s += __expf(vv[e] - t0);

        float g1 = 1.0f / s, g2 = __expf(t1 - t0) / s;
        int i1 = j0, i2 = j1;

        const bool flag = (t0 - t1 < TH) || (t1 - t2 < TH);
        const bool deep = (t1 - t3 < TH);
        unsigned fb = __ballot_sync(FULL, flag);
        const unsigned db = __ballot_sync(FULL, deep);

        while (fb) {
            const int b = __ffs(fb) - 1; fb &= fb - 1;
            const int tk = bm + 64 + mwid * 32 + b;
            const float* xr = x + (size_t)tk * K_DIM;
            float em1, em2, ns; int ei1, ei2;

            if ((db >> b) & 1) {
                const int e0 = lid * 2, e1 = e0 + 1;
                const float* w0 = Wm + (size_t)e0 * K_DIM;
                const float* w1 = Wm + (size_t)e1 * K_DIM;
                float a0 = 0.f, a1 = 0.f;
                #pragma unroll 2
                for (int k = 0; k < K_DIM; k += 4) {
                    const float4 xq = *(const float4*)(xr + k);
                    const float4 v0 = *(const float4*)(w0 + k);
                    const float4 v1 = *(const float4*)(w1 + k);
                    a0 = fmaf(xq.x, v0.x, a0); a0 = fmaf(xq.y, v0.y, a0);
                    a0 = fmaf(xq.z, v0.z, a0); a0 = fmaf(xq.w, v0.w, a0);
                    a1 = fmaf(xq.x, v1.x, a1); a1 = fmaf(xq.y, v1.y, a1);
                    a1 = fmaf(xq.z, v1.z, a1); a1 = fmaf(xq.w, v1.w, a1);
                }
                a0 += __ldg(bias + e0); a1 += __ldg(bias + e1);
                float fm1, fm2; int fi1, fi2;
                if (a0 >= a1) { fm1 = a0; fi1 = e0; fm2 = a1; fi2 = e1; }
                else          { fm1 = a1; fi1 = e1; fm2 = a0; fi2 = e0; }
                #pragma unroll
                for (int d = 1; d < 32; d <<= 1) {
                    const float om1 = __shfl_xor_sync(FULL, fm1, d);
                    const float om2 = __shfl_xor_sync(FULL, fm2, d);
                    const int   oi1 = __shfl_xor_sync(FULL, fi1, d);
                    const int   oi2 = __shfl_xor_sync(FULL, fi2, d);
                    if (om1 > fm1) {
                        if (fm1 > om2) { fm2 = fm1; fi2 = fi1; }
                        else           { fm2 = om2; fi2 = oi2; }
                        fm1 = om1; fi1 = oi1;
                    } else if (om1 > fm2) { fm2 = om1; fi2 = oi1; }
                }
                float fs = __expf(a0 - fm1) + __expf(a1 - fm1);
                #pragma unroll
                for (int d = 1; d < 32; d <<= 1)
                    fs += __shfl_xor_sync(FULL, fs, d);
                em1 = fm1; ei1 = fi1; em2 = fm2; ei2 = fi2; ns = fs;
            } else {
                const float qm = __shfl_sync(FULL, t0, b);
                const float qs = __shfl_sync(FULL, s, b);
                int qi[4];
                qi[0] = __shfl_sync(FULL, j0, b);
                qi[1] = __shfl_sync(FULL, j1, b);
                qi[2] = __shfl_sync(FULL, j2, b);
                qi[3] = __shfl_sync(FULL, j3, b);
                float ds[4] = {0.f, 0.f, 0.f, 0.f};
                #pragma unroll
                for (int u = 0; u < 8; ++u) {
                    const int k = u * 128 + lid * 4;
                    const float4 xq = *(const float4*)(xr + k);
                    #pragma unroll
                    for (int q = 0; q < 4; ++q) {
                        const float4 wq = *(const float4*)(Wm + (size_t)qi[q] * K_DIM + k);
                        ds[q] = fmaf(xq.x, wq.x, ds[q]);
                        ds[q] = fmaf(xq.y, wq.y, ds[q]);
                        ds[q] = fmaf(xq.z, wq.z, ds[q]);
                        ds[q] = fmaf(xq.w, wq.w, ds[q]);
                    }
                }
                #pragma unroll
                for (int d = 1; d < 32; d <<= 1) {
                    #pragma unroll
                    for (int q = 0; q < 4; ++q)
                        ds[q] += __shfl_xor_sync(FULL, ds[q], d);
                }
                #pragma unroll
                for (int q = 0; q < 4; ++q) ds[q] += __ldg(bias + qi[q]);
                em1 = ds[0]; ei1 = qi[0]; em2 = -INFINITY; ei2 = 0;
                #pragma unroll
                for (int q = 1; q < 4; ++q) {
                    if (ds[q] > em1) { em2 = em1; ei2 = ei1; em1 = ds[q]; ei1 = qi[q]; }
                    else if (ds[q] > em2) { em2 = ds[q]; ei2 = qi[q]; }
                }
                ns = qs * __expf(qm - em1);
            }
            if (lid == b) {
                g1 = 1.0f / ns; g2 = __expf(em2 - em1) / ns;
                i1 = ei1; i2 = ei2;
            }
        }

        const int tk = bm + 64 + ltk;
        *(float2*)&out[tk * 2] = make_float2(g1, g2);
        *(float2*)&oid[tk * 2] = make_float2((float)i1, (float)i2);
    }
}

extern "C" void kernel_launch(void* const* d_in, const int* in_sizes, int n_in,
                              void* d_out, int out_size) {
    const float* x = (const float*)d_in[0];   // [8,4096,1024]
    const float* W = (const float*)d_in[1];   // [64,1024]
    const float* b = (const float*)d_in[2];   // [64]
    float* out = (float*)d_out;

    const int num_tokens = in_sizes[0] / K_DIM;   // 32768
    const int grid = num_tokens / BM;             // 256

    cudaFuncSetAttribute(router_dual_kernel,
                         cudaFuncAttributeMaxDynamicSharedMemorySize, SMEM_FLOATS * 4);
    router_dual_kernel<<<grid, 256, SMEM_FLOATS * 4>>>(x, W, b, out, num_tokens);
}

// round 15
// speedup vs baseline: 1.0076x; 1.0076x over previous
#include <cuda_runtime.h>
#include <cstdint>
#include <math.h>

#define K_DIM 1024
#define N_EXPERTS 64
#define BM 128
#define KCHUNK 16
#define NCHUNK 64
// FFMA group: 2 stages of (xs[16][68] + ws[16][68]) = 2*2176 floats
#define F_K_STRIDE 68
#define F_STAGE 2176
#define F_REGION (2 * F_STAGE)          // 4352 floats (also holds lg[64][68])
// MMA group: 2 stages of (xs[64][36] + ws[64][36]) = 2*4608 floats
#define M_STRIDE 36
#define M_STAGE 4608
#define M_REGION (2 * M_STAGE)          // 9216 floats
#define LG_STRIDE 68
#define SMEM_FLOATS (F_REGION + M_REGION)   // 13568 -> 54272 B
#define TH 7e-3f
#define FULL 0xffffffffu

#define GBAR(id) asm volatile("bar.sync %0, 128;" :: "r"(id) : "memory")

#define MMA_TF32(d, a, b) \
    asm volatile("mma.sync.aligned.m16n8k8.row.col.f32.tf32.tf32.f32 " \
        "{%0,%1,%2,%3}, {%4,%5,%6,%7}, {%8,%9}, {%0,%1,%2,%3};" \
        : "+f"((d)[0]), "+f"((d)[1]), "+f"((d)[2]), "+f"((d)[3]) \
        : "r"((a)[0]), "r"((a)[1]), "r"((a)[2]), "r"((a)[3]), "r"((b)[0]), "r"((b)[1]))

#define INS4(vv, ii) do {                                                     \
    const float _v = (vv); const int _i = (ii);                               \
    if (_v > t3) {                                                            \
        if (_v > t2) { t3 = t2; j3 = j2;                                      \
            if (_v > t1) { t2 = t1; j2 = j1;                                  \
                if (_v > t0) { t1 = t0; j1 = j0; t0 = _v; j0 = _i; }          \
                else         { t1 = _v; j1 = _i; } }                          \
            else { t2 = _v; j2 = _i; } }                                      \
        else { t3 = _v; j3 = _i; } }                                          \
} while (0)

__global__ __launch_bounds__(256, 2)
void router_dual2_kernel(const float* __restrict__ x,
                         const float* __restrict__ Wm,
                         const float* __restrict__ bias,
                         float* __restrict__ out,
                         int num_tokens) {
    extern __shared__ float smem[];
    const int tid  = threadIdx.x;
    const int gid  = tid >> 7;          // 0 = FFMA group, 1 = MMA group
    const int gtid = tid & 127;
    const int lid  = tid & 31;
    const int bm   = blockIdx.x * BM;
    float* oid = out + (size_t)num_tokens * 2;
    const float4* b4 = (const float4*)bias;

    if (gid == 0) {
        // ========== FFMA group: tokens [bm, bm+64) x 64 experts, exact fp32 ==========
        const int row = gtid;                 // 0..63: x rows; 64..127: W rows
        const int col = row & 63;
        const int tym = gtid >> 3;            // tokens tym*4..+3
        const int txk = gtid & 7;             // experts txk*8..+7
        const float* grow = (row < 64) ? (x + (size_t)(bm + row) * K_DIM)
                                       : (Wm + (size_t)(row - 64) * K_DIM);

        float4 st[4];
        auto ldg_chunk = [&](int c) {
            #pragma unroll
            for (int j = 0; j < 4; ++j)
                st[j] = __ldg((const float4*)(grow + c * KCHUNK + j * 4));
        };
        auto sts_chunk = [&](int buf) {
            float* base = smem + buf * F_STAGE + ((row < 64) ? 0 : KCHUNK * F_K_STRIDE);
            #pragma unroll
            for (int j = 0; j < 4; ++j) {
                base[(j * 4 + 0) * F_K_STRIDE + col] = st[j].x;
                base[(j * 4 + 1) * F_K_STRIDE + col] = st[j].y;
                base[(j * 4 + 2) * F_K_STRIDE + col] = st[j].z;
                base[(j * 4 + 3) * F_K_STRIDE + col] = st[j].w;
            }
        };

        float acc[4][8];
        #pragma unroll
        for (int i = 0; i < 4; ++i)
            #pragma unroll
            for (int j = 0; j < 8; ++j) acc[i][j] = 0.0f;

        ldg_chunk(0);
        sts_chunk(0);
        GBAR(1);

        #pragma unroll 1
        for (int c = 0; c < NCHUNK; ++c) {
            if (c + 1 < NCHUNK) ldg_chunk(c + 1);

            const float* xs = smem + (c & 1) * F_STAGE;
            const float* ws = xs + KCHUNK * F_K_STRIDE;

            #pragma unroll 4
            for (int k = 0; k < KCHUNK; ++k) {
                const float4 a  = *(const float4*)&xs[k * F_K_STRIDE + tym * 4];
                const float4 b0 = *(const float4*)&ws[k * F_K_STRIDE + txk * 8];
                const float4 b1 = *(const float4*)&ws[k * F_K_STRIDE + txk * 8 + 4];
                const float am[4] = {a.x, a.y, a.z, a.w};
                const float bn[8] = {b0.x, b0.y, b0.z, b0.w, b1.x, b1.y, b1.z, b1.w};
                #pragma unroll
                for (int i = 0; i < 4; ++i)
                    #pragma unroll
                    for (int j = 0; j < 8; ++j)
                        acc[i][j] = fmaf(am[i], bn[j], acc[i][j]);
            }
            if (c + 1 < NCHUNK) sts_chunk((c + 1) & 1);
            GBAR(1);
        }

        // dump logits [64][68] into the group's region
        float* lg = smem;
        #pragma unroll
        for (int i = 0; i < 4; ++i)
            #pragma unroll
            for (int j = 0; j < 8; ++j)
                lg[(tym * 4 + i) * LG_STRIDE + txk * 8 + j] = acc[i][j];
        GBAR(1);
        if (gtid >= 64) return;

        const float4* lrow = (const float4*)&lg[gtid * LG_STRIDE];
        float v[64];
        #pragma unroll
        for (int q = 0; q < 16; ++q) {
            const float4 lv = lrow[q];
            const float4 bv = __ldg(b4 + q);
            v[q * 4 + 0] = lv.x + bv.x;
            v[q * 4 + 1] = lv.y + bv.y;
            v[q * 4 + 2] = lv.z + bv.z;
            v[q * 4 + 3] = lv.w + bv.w;
        }
        float m1 = -INFINITY, m2 = -INFINITY;
        int i1 = 0, i2 = 0;
        #pragma unroll
        for (int e = 0; e < 64; ++e) {
            if (v[e] > m1) { m2 = m1; i2 = i1; m1 = v[e]; i1 = e; }
            else if (v[e] > m2) { m2 = v[e]; i2 = e; }
        }
        float s = 0.0f;
        #pragma unroll
        for (int e = 0; e < 64; ++e) s += __expf(v[e] - m1);

        const float inv = 1.0f / s;
        const int tk = bm + gtid;
        *(float2*)&out[tk * 2] = make_float2(inv, __expf(m2 - m1) * inv);
        *(float2*)&oid[tk * 2] = make_float2((float)i1, (float)i2);
        return;
    }

    // ========== MMA group: tokens [bm+64, bm+128) x 64 experts, tf32 + fixup ==========
    {
        const int row  = gtid;                // 0..63: x rows; 64..127: W rows
        const int mwid = gtid >> 5;
        const int r  = lid >> 2;
        const int cq = lid & 3;
        const float* grow = (row < 64) ? (x + (size_t)(bm + 64 + row) * K_DIM)
                                       : (Wm + (size_t)(row - 64) * K_DIM);
        const int doff = ((row < 64) ? 0 : 64 * M_STRIDE) + (row & 63) * M_STRIDE;

        float4 st[4];
        auto ldg_chunk = [&](int c) {
            #pragma unroll
            for (int j = 0; j < 4; ++j)
                st[j] = __ldg((const float4*)(grow + c * KCHUNK + j * 4));
        };
        auto sts_chunk = [&](int buf) {
            float* dst = smem + F_REGION + buf * M_STAGE + doff;
            #pragma unroll
            for (int j = 0; j < 4; ++j)
                *(float4*)&dst[j * 4] = st[j];
        };

        float acc[4][2][4];
        #pragma unroll
        for (int mt = 0; mt < 4; ++mt)
            #pragma unroll
            for (int nt = 0; nt < 2; ++nt)
                #pragma unroll
                for (int q = 0; q < 4; ++q) acc[mt][nt][q] = 0.0f;

        ldg_chunk(0);
        sts_chunk(0);
        GBAR(2);

        #pragma unroll 1
        for (int c = 0; c < NCHUNK; ++c) {
            if (c + 1 < NCHUNK) ldg_chunk(c + 1);

            const uint32_t* xsp = (const uint32_t*)(smem + F_REGION + (c & 1) * M_STAGE);
            const uint32_t* wsp = xsp + 64 * M_STRIDE;

            #pragma unroll
            for (int ks = 0; ks < 2; ++ks) {
                const int kc = ks * 8 + cq;
                uint32_t bf[2][2], af[4][4];
                #pragma unroll
                for (int nt = 0; nt < 2; ++nt) {
                    const int tr = mwid * 16 + nt * 8 + r;
                    bf[nt][0] = xsp[tr * M_STRIDE + kc];
                    bf[nt][1] = xsp[tr * M_STRIDE + kc + 4];
                }
                #pragma unroll
                for (int mt = 0; mt < 4; ++mt) {
                    const int er = mt * 16 + r;
                    af[mt][0] = wsp[er * M_STRIDE + kc];
                    af[mt][1] = wsp[(er + 8) * M_STRIDE + kc];
                    af[mt][2] = wsp[er * M_STRIDE + kc + 4];
                    af[mt][3] = wsp[(er + 8) * M_STRIDE + kc + 4];
                }
                #pragma unroll
                for (int mt = 0; mt < 4; ++mt)
                    #pragma unroll
                    for (int nt = 0; nt < 2; ++nt)
                        MMA_TF32(acc[mt][nt], af[mt], bf[nt]);
            }
            if (c + 1 < NCHUNK) sts_chunk((c + 1) & 1);
            GBAR(2);
        }

        // dump logits [64][68] into MMA region
        float* lg = smem + F_REGION;
        #pragma unroll
        for (int mt = 0; mt < 4; ++mt)
            #pragma unroll
            for (int nt = 0; nt < 2; ++nt)
                #pragma unroll
                for (int q = 0; q < 4; ++q) {
                    const int tr = mwid * 16 + nt * 8 + 2 * cq + (q & 1);
                    const int e  = mt * 16 + r + (q >> 1) * 8;
                    lg[tr * LG_STRIDE + e] = acc[mt][nt][q];
                }
        GBAR(2);
        if (mwid >= 2) return;

        const int ltk = mwid * 32 + lid;
        const float4* lrow = (const float4*)&lg[ltk * LG_STRIDE];

        float t0 = -INFINITY, t1 = -INFINITY, t2 = -INFINITY, t3 = -INFINITY;
        int j0 = 0, j1 = 0, j2 = 0, j3 = 0;
        float vv[64];
        #pragma unroll
        for (int q = 0; q < 16; ++q) {
            const float4 lv = lrow[q];
            const float4 bv = __ldg(b4 + q);
            vv[q * 4 + 0] = lv.x + bv.x;
            vv[q * 4 + 1] = lv.y + bv.y;
            vv[q * 4 + 2] = lv.z + bv.z;
            vv[q * 4 + 3] = lv.w + bv.w;
        }
        #pragma unroll
        for (int e = 0; e < 64; ++e) INS4(vv[e], e);

        float s = 0.0f;
        #pragma unroll
        for (int e = 0; e < 64; ++e) s += __expf(vv[e] - t0);

        float g1 = 1.0f / s, g2 = __expf(t1 - t0) / s;
        int i1 = j0, i2 = j1;

        const bool flag = (t0 - t1 < TH) || (t1 - t2 < TH);
        const bool deep = (t1 - t3 < TH);
        unsigned fb = __ballot_sync(FULL, flag);
        const unsigned db = __ballot_sync(FULL, deep);

        while (fb) {
            const int b = __ffs(fb) - 1; fb &= fb - 1;
            const int tk = bm + 64 + mwid * 32 + b;
            const float* xr = x + (size_t)tk * K_DIM;
            float em1, em2, ns; int ei1, ei2;

            if ((db >> b) & 1) {
                const int e0 = lid * 2, e1 = e0 + 1;
                const float* w0 = Wm + (size_t)e0 * K_DIM;
                const float* w1 = Wm + (size_t)e1 * K_DIM;
                float a0 = 0.f, a1 = 0.f;
                #pragma unroll 2
                for (int k = 0; k < K_DIM; k += 4) {
                    const float4 xq = *(const float4*)(xr + k);
                    const float4 v0 = *(const float4*)(w0 + k);
                    const float4 v1 = *(const float4*)(w1 + k);
                    a0 = fmaf(xq.x, v0.x, a0); a0 = fmaf(xq.y, v0.y, a0);
                    a0 = fmaf(xq.z, v0.z, a0); a0 = fmaf(xq.w, v0.w, a0);
                    a1 = fmaf(xq.x, v1.x, a1); a1 = fmaf(xq.y, v1.y, a1);
                    a1 = fmaf(xq.z, v1.z, a1); a1 = fmaf(xq.w, v1.w, a1);
                }
                a0 += __ldg(bias + e0); a1 += __ldg(bias + e1);
                float fm1, fm2; int fi1, fi2;
                if (a0 >= a1) { fm1 = a0; fi1 = e0; fm2 = a1; fi2 = e1; }
                else          { fm1 = a1; fi1 = e1; fm2 = a0; fi2 = e0; }
                #pragma unroll
                for (int d = 1; d < 32; d <<= 1) {
                    const float om1 = __shfl_xor_sync(FULL, fm1, d);
                    const float om2 = __shfl_xor_sync(FULL, fm2, d);
                    const int   oi1 = __shfl_xor_sync(FULL, fi1, d);
                    const int   oi2 = __shfl_xor_sync(FULL, fi2, d);
                    if (om1 > fm1) {
                        if (fm1 > om2) { fm2 = fm1; fi2 = fi1; }
                        else           { fm2 = om2; fi2 = oi2; }
                        fm1 = om1; fi1 = oi1;
                    } else if (om1 > fm2) { fm2 = om1; fi2 = oi1; }
                }
                float fs = __expf(a0 - fm1) + __expf(a1 - fm1);
                #pragma unroll
                for (int d = 1; d < 32; d <<= 1)
                    fs += __shfl_xor_sync(FULL, fs, d);
                em1 = fm1; ei1 = fi1; em2 = fm2; ei2 = fi2; ns = fs;
            } else {
                const float qm = __shfl_sync(FULL, t0, b);
                const float qs = __shfl_sync(FULL, s, b);
                int qi[4];
                qi[0] = __shfl_sync(FULL, j0, b);
                qi[1] = __shfl_sync(FULL, j1, b);
                qi[2] = __shfl_sync(FULL, j2, b);
                qi[3] = __shfl_sync(FULL, j3, b);
                float ds[4] = {0.f, 0.f, 0.f, 0.f};
                #pragma unroll
                for (int u = 0; u < 8; ++u) {
                    const int k = u * 128 + lid * 4;
                    const float4 xq = *(const float4*)(xr + k);
                    #pragma unroll
                    for (int q = 0; q < 4; ++q) {
                        const float4 wq = *(const float4*)(Wm + (size_t)qi[q] * K_DIM + k);
                        ds[q] = fmaf(xq.x, wq.x, ds[q]);
                        ds[q] = fmaf(xq.y, wq.y, ds[q]);
                        ds[q] = fmaf(xq.z, wq.z, ds[q]);
                        ds[q] = fmaf(xq.w, wq.w, ds[q]);
                    }
                }
                #pragma unroll
                for (int d = 1; d < 32; d <<= 1) {
                    #pragma unroll
                    for (int q = 0; q < 4; ++q)
                        ds[q] += __shfl_xor_sync(FULL, ds[q], d);
                }
                #pragma unroll
                for (int q = 0; q < 4; ++q) ds[q] += __ldg(bias + qi[q]);
                em1 = ds[0]; ei1 = qi[0]; em2 = -INFINITY; ei2 = 0;
                #pragma unroll
                for (int q = 1; q < 4; ++q) {
                    if (ds[q] > em1) { em2 = em1; ei2 = ei1; em1 = ds[q]; ei1 = qi[q]; }
                    else if (ds[q] > em2) { em2 = ds[q]; ei2 = qi[q]; }
                }
                ns = qs * __expf(qm - em1);
            }
            if (lid == b) {
                g1 = 1.0f / ns; g2 = __expf(em2 - em1) / ns;
                i1 = ei1; i2 = ei2;
            }
        }

        const int tk = bm + 64 + ltk;
        *(float2*)&out[tk * 2] = make_float2(g1, g2);
        *(float2*)&oid[tk * 2] = make_float2((float)i1, (float)i2);
    }
}

extern "C" void kernel_launch(void* const* d_in, const int* in_sizes, int n_in,
                              void* d_out, int out_size) {
    const float* x = (const float*)d_in[0];   // [8,4096,1024]
    const float* W = (const float*)d_in[1];   // [64,1024]
    const float* b = (const float*)d_in[2];   // [64]
    float* out = (float*)d_out;

    const int num_tokens = in_sizes[0] / K_DIM;   // 32768
    const int grid = num_tokens / BM;             // 256

    cudaFuncSetAttribute(router_dual2_kernel,
                         cudaFuncAttributeMaxDynamicSharedMemorySize, SMEM_FLOATS * 4);
    router_dual2_kernel<<<grid, 256, SMEM_FLOATS * 4>>>(x, W, b, out, num_tokens);
}

// round 16
// speedup vs baseline: 1.6653x; 1.6527x over previous
#include <cuda_runtime.h>
#include <cstdint>
#include <math.h>

#define K_DIM 1024
#define N_EXPERTS 64
#define BM 128
#define KCHUNK 16
#define NLOCAL 32                 // chunks per group (512 K each)
#define XS_STRIDE 132             // [k][token] floats
#define WS_STRIDE 68              // [k][expert] floats
#define XS_FLOATS (KCHUNK * XS_STRIDE)             // 2112
#define GRP_FLOATS (KCHUNK * (XS_STRIDE + WS_STRIDE))  // 3200
#define LG_STRIDE 68
#define SMEM_FLOATS 8704
#define FULL 0xffffffffu

#define GBAR(id) asm volatile("bar.sync %0, 128;" :: "r"(id) : "memory")

__global__ __launch_bounds__(256, 2)
void router_splitk3_kernel(const float* __restrict__ x,
                           const float* __restrict__ Wm,
                           const float* __restrict__ bias,
                           float* __restrict__ out,
                           int num_tokens) {
    extern __shared__ float smem[];
    const int tid  = threadIdx.x;
    const int gid  = tid >> 7;          // k-split group 0/1
    const int gtid = tid & 127;
    const int bm   = blockIdx.x * BM;
    const int kbase = gid * (K_DIM / 2);

    float* xs = smem + gid * GRP_FLOATS;         // [16][132]
    float* ws = xs + XS_FLOATS;                  // [16][68]

    // loader mapping: kq = k-granule 0..3, row = 0..31
    const int kq  = gtid & 3;
    const int row = gtid >> 2;

    // compute mapping: txk = expert oct 0..7, tym = token oct 0..15
    const int txk = gtid & 7;
    const int tym = gtid >> 3;

    // staging registers for the hoisted LDG
    float4 xv[4], wv[2];
    auto ldg_chunk = [&](int c) {
        const int ko = kbase + c * KCHUNK + kq * 4;
        const float* gx = x + (size_t)(bm + row) * K_DIM + ko;
        #pragma unroll
        for (int i = 0; i < 4; ++i)
            xv[i] = __ldg((const float4*)(gx + (size_t)(32 * i) * K_DIM));
        const float* gw = Wm + (size_t)row * K_DIM + ko;
        #pragma unroll
        for (int i = 0; i < 2; ++i)
            wv[i] = __ldg((const float4*)(gw + (size_t)(32 * i) * K_DIM));
    };
    auto sts_chunk = [&]() {
        #pragma unroll
        for (int i = 0; i < 4; ++i) {
            xs[(kq * 4 + 0) * XS_STRIDE + row + 32 * i] = xv[i].x;
            xs[(kq * 4 + 1) * XS_STRIDE + row + 32 * i] = xv[i].y;
            xs[(kq * 4 + 2) * XS_STRIDE + row + 32 * i] = xv[i].z;
            xs[(kq * 4 + 3) * XS_STRIDE + row + 32 * i] = xv[i].w;
        }
        #pragma unroll
        for (int i = 0; i < 2; ++i) {
            ws[(kq * 4 + 0) * WS_STRIDE + row + 32 * i] = wv[i].x;
            ws[(kq * 4 + 1) * WS_STRIDE + row + 32 * i] = wv[i].y;
            ws[(kq * 4 + 2) * WS_STRIDE + row + 32 * i] = wv[i].z;
            ws[(kq * 4 + 3) * WS_STRIDE + row + 32 * i] = wv[i].w;
        }
    };

    float acc[8][8];
    #pragma unroll
    for (int i = 0; i < 8; ++i)
        #pragma unroll
        for (int j = 0; j < 8; ++j) acc[i][j] = 0.0f;

    const int barid = 1 + gid;

    ldg_chunk(0);
    sts_chunk();
    GBAR(barid);

    #pragma unroll 1
    for (int c = 0; c < NLOCAL; ++c) {
        // hoist next chunk's LDG before compute: latency hidden under FFMA
        if (c + 1 < NLOCAL) ldg_chunk(c + 1);

        #pragma unroll 4
        for (int k = 0; k < KCHUNK; ++k) {
            const float4 a0 = *(const float4*)&xs[k * XS_STRIDE + tym * 8];
            const float4 a1 = *(const float4*)&xs[k * XS_STRIDE + tym * 8 + 4];
            const float4 b0 = *(const float4*)&ws[k * WS_STRIDE + txk * 8];
            const float4 b1 = *(const float4*)&ws[k * WS_STRIDE + txk * 8 + 4];
            const float am[8] = {a0.x, a0.y, a0.z, a0.w, a1.x, a1.y, a1.z, a1.w};
            const float bn[8] = {b0.x, b0.y, b0.z, b0.w, b1.x, b1.y, b1.z, b1.w};
            #pragma unroll
            for (int i = 0; i < 8; ++i)
                #pragma unroll
                for (int j = 0; j < 8; ++j)
                    acc[i][j] = fmaf(am[i], bn[j], acc[i][j]);
        }
        GBAR(barid);
        if (c + 1 < NLOCAL) {
            sts_chunk();              // only the cheap STS is exposed now
            GBAR(barid);
        }
    }

    // ---- merge k-split partials ----
    __syncthreads();
    if (gid == 1) {
        #pragma unroll
        for (int i = 0; i < 8; ++i)
            #pragma unroll
            for (int j = 0; j < 8; ++j)
                smem[gtid * 65 + i * 8 + j] = acc[i][j];
    }
    __syncthreads();
    if (gid != 0) return;

    #pragma unroll
    for (int i = 0; i < 8; ++i)
        #pragma unroll
        for (int j = 0; j < 8; ++j)
            acc[i][j] += smem[gtid * 65 + i * 8 + j];
    GBAR(1);

    // ---- dump summed logits [token][expert] ----
    #pragma unroll
    for (int i = 0; i < 8; ++i)
        #pragma unroll
        for (int j = 0; j < 8; ++j)
            smem[(tym * 8 + i) * LG_STRIDE + txk * 8 + j] = acc[i][j];
    GBAR(1);

    // ---- exact per-token epilogue: thread gtid owns token bm+gtid ----
    const float4* b4 = (const float4*)bias;
    const float4* lrow = (const float4*)&smem[gtid * LG_STRIDE];

    float v[64];
    #pragma unroll
    for (int q = 0; q < 16; ++q) {
        const float4 lv = lrow[q];
        const float4 bv = __ldg(b4 + q);
        v[q * 4 + 0] = lv.x + bv.x;
        v[q * 4 + 1] = lv.y + bv.y;
        v[q * 4 + 2] = lv.z + bv.z;
        v[q * 4 + 3] = lv.w + bv.w;
    }
    float m1 = -INFINITY, m2 = -INFINITY;
    int i1 = 0, i2 = 0;
    #pragma unroll
    for (int e = 0; e < 64; ++e) {
        if (v[e] > m1) { m2 = m1; i2 = i1; m1 = v[e]; i1 = e; }
        else if (v[e] > m2) { m2 = v[e]; i2 = e; }
    }
    float s = 0.0f;
    #pragma unroll
    for (int e = 0; e < 64; ++e) s += __expf(v[e] - m1);

    const float inv = 1.0f / s;
    const int tk = bm + gtid;
    float* oid = out + (size_t)num_tokens * 2;
    *(float2*)&out[tk * 2] = make_float2(inv, __expf(m2 - m1) * inv);
    *(float2*)&oid[tk * 2] = make_float2((float)i1, (float)i2);
}

extern "C" void kernel_launch(void* const* d_in, const int* in_sizes, int n_in,
                              void* d_out, int out_size) {
    const float* x = (const float*)d_in[0];   // [8,4096,1024]
    const float* W = (const float*)d_in[1];   // [64,1024]
    const float* b = (const float*)d_in[2];   // [64]
    float* out = (float*)d_out;

    const int num_tokens = in_sizes[0] / K_DIM;   // 32768
    const int grid = num_tokens / BM;             // 256

    cudaFuncSetAttribute(router_splitk3_kernel,
                         cudaFuncAttributeMaxDynamicSharedMemorySize, SMEM_FLOATS * 4);
    router_splitk3_kernel<<<grid, 256, SMEM_FLOATS * 4>>>(x, W, b, out, num_tokens);
}

// round 17
// speedup vs baseline: 1.9587x; 1.1762x over previous
#include <cuda_runtime.h>
#include <cstdint>
#include <math.h>

#define K_DIM 1024
#define N_EXPERTS 64
#define KCHUNK 16
#define NLOCAL 32                 // chunks per group (512 K each)
#define XS_STRIDE 132             // [k][token] floats
#define WS_STRIDE 68              // [k][expert] floats
#define XS_FLOATS (KCHUNK * XS_STRIDE)             // 2112
#define GRP_FLOATS (KCHUNK * (XS_STRIDE + WS_STRIDE))  // 3200
#define LG_STRIDE 68
#define SMEM_FLOATS 8704
#define FULL 0xffffffffu

// mixed grid: 296 blocks = 136 x BM128 + 160 x BM96, paired (128,96) per SM
#define NBIG 136
#define HALF 148
#define BIG_TOK (NBIG * 128)                 // 17408
#define H1_TOK (BIG_TOK + (HALF - NBIG) * 96)  // 18560

#define GBAR(id) asm volatile("bar.sync %0, 128;" :: "r"(id) : "memory")

__global__ __launch_bounds__(256, 2)
void router_mixed_kernel(const float* __restrict__ x,
                         const float* __restrict__ Wm,
                         const float* __restrict__ bias,
                         float* __restrict__ out,
                         int num_tokens) {
    extern __shared__ float smem[];
    const int tid  = threadIdx.x;
    const int gid  = tid >> 7;          // k-split group 0/1
    const int gtid = tid & 127;
    const int bid  = blockIdx.x;

    // ---- block -> (token offset, BM) ----
    int bm, BMv;
    if (bid < HALF) {
        if (bid < NBIG) { bm = bid * 128;                      BMv = 128; }
        else            { bm = BIG_TOK + (bid - NBIG) * 96;    BMv = 96;  }
    } else {
        bm = H1_TOK + (bid - HALF) * 96;                       BMv = 96;
    }
    const int cap = BMv >> 3;           // 16 or 12 token-octs
    const int nxi = BMv >> 5;           // 4 or 3 x-row groups

    const int kbase = gid * (K_DIM / 2);
    float* xs = smem + gid * GRP_FLOATS;         // [16][132]
    float* ws = xs + XS_FLOATS;                  // [16][68]

    // loader mapping: kq = k-granule 0..3, row = 0..31
    const int kq  = gtid & 3;
    const int row = gtid >> 2;

    // compute mapping: txk = expert oct 0..7, tym = token oct 0..15
    const int txk = gtid & 7;
    const int tym = gtid >> 3;

    auto load_chunk = [&](int c) {
        const int ko = kbase + c * KCHUNK + kq * 4;
        float4 xv[4], wv[2];
        const float* gx = x + (size_t)(bm + row) * K_DIM + ko;
        for (int i = 0; i < nxi; ++i)
            xv[i] = __ldg((const float4*)(gx + (size_t)(32 * i) * K_DIM));
        const float* gw = Wm + (size_t)row * K_DIM + ko;
        #pragma unroll
        for (int i = 0; i < 2; ++i)
            wv[i] = __ldg((const float4*)(gw + (size_t)(32 * i) * K_DIM));
        for (int i = 0; i < nxi; ++i) {
            xs[(kq * 4 + 0) * XS_STRIDE + row + 32 * i] = xv[i].x;
            xs[(kq * 4 + 1) * XS_STRIDE + row + 32 * i] = xv[i].y;
            xs[(kq * 4 + 2) * XS_STRIDE + row + 32 * i] = xv[i].z;
            xs[(kq * 4 + 3) * XS_STRIDE + row + 32 * i] = xv[i].w;
        }
        #pragma unroll
        for (int i = 0; i < 2; ++i) {
            ws[(kq * 4 + 0) * WS_STRIDE + row + 32 * i] = wv[i].x;
            ws[(kq * 4 + 1) * WS_STRIDE + row + 32 * i] = wv[i].y;
            ws[(kq * 4 + 2) * WS_STRIDE + row + 32 * i] = wv[i].z;
            ws[(kq * 4 + 3) * WS_STRIDE + row + 32 * i] = wv[i].w;
        }
    };

    float acc[8][8];
    #pragma unroll
    for (int i = 0; i < 8; ++i)
        #pragma unroll
        for (int j = 0; j < 8; ++j) acc[i][j] = 0.0f;

    const int barid = 1 + gid;

    load_chunk(0);
    GBAR(barid);

    #pragma unroll 1
    for (int c = 0; c < NLOCAL; ++c) {
        if (tym < cap) {              // warp-uniform: BM=96 idles warp 3 of each group
            #pragma unroll 4
            for (int k = 0; k < KCHUNK; ++k) {
                const float4 a0 = *(const float4*)&xs[k * XS_STRIDE + tym * 8];
                const float4 a1 = *(const float4*)&xs[k * XS_STRIDE + tym * 8 + 4];
                const float4 b0 = *(const float4*)&ws[k * WS_STRIDE + txk * 8];
                const float4 b1 = *(const float4*)&ws[k * WS_STRIDE + txk * 8 + 4];
                const float am[8] = {a0.x, a0.y, a0.z, a0.w, a1.x, a1.y, a1.z, a1.w};
                const float bn[8] = {b0.x, b0.y, b0.z, b0.w, b1.x, b1.y, b1.z, b1.w};
                #pragma unroll
                for (int i = 0; i < 8; ++i)
                    #pragma unroll
                    for (int j = 0; j < 8; ++j)
                        acc[i][j] = fmaf(am[i], bn[j], acc[i][j]);
            }
        }
        GBAR(barid);
        if (c + 1 < NLOCAL) {
            load_chunk(c + 1);
            GBAR(barid);
        }
    }

    // ---- merge k-split partials (idle warps carry zeros; harmless) ----
    __syncthreads();
    if (gid == 1) {
        #pragma unroll
        for (int i = 0; i < 8; ++i)
            #pragma unroll
            for (int j = 0; j < 8; ++j)
                smem[gtid * 65 + i * 8 + j] = acc[i][j];
    }
    __syncthreads();
    if (gid != 0) return;

    #pragma unroll
    for (int i = 0; i < 8; ++i)
        #pragma unroll
        for (int j = 0; j < 8; ++j)
            acc[i][j] += smem[gtid * 65 + i * 8 + j];
    GBAR(1);

    // ---- dump summed logits [token][expert] ----
    #pragma unroll
    for (int i = 0; i < 8; ++i)
        #pragma unroll
        for (int j = 0; j < 8; ++j)
            smem[(tym * 8 + i) * LG_STRIDE + txk * 8 + j] = acc[i][j];
    GBAR(1);

    if (gtid >= BMv) return;

    // ---- exact per-token epilogue: thread gtid owns token bm+gtid ----
    const float4* b4 = (const float4*)bias;
    const float4* lrow = (const float4*)&smem[gtid * LG_STRIDE];

    float v[64];
    #pragma unroll
    for (int q = 0; q < 16; ++q) {
        const float4 lv = lrow[q];
        const float4 bv = __ldg(b4 + q);
        v[q * 4 + 0] = lv.x + bv.x;
        v[q * 4 + 1] = lv.y + bv.y;
        v[q * 4 + 2] = lv.z + bv.z;
        v[q * 4 + 3] = lv.w + bv.w;
    }
    float m1 = -INFINITY, m2 = -INFINITY;
    int i1 = 0, i2 = 0;
    #pragma unroll
    for (int e = 0; e < 64; ++e) {
        if (v[e] > m1) { m2 = m1; i2 = i1; m1 = v[e]; i1 = e; }
        else if (v[e] > m2) { m2 = v[e]; i2 = e; }
    }
    float s = 0.0f;
    #pragma unroll
    for (int e = 0; e < 64; ++e) s += __expf(v[e] - m1);

    const float inv = 1.0f / s;
    const int tk = bm + gtid;
    float* oid = out + (size_t)num_tokens * 2;
    *(float2*)&out[tk * 2] = make_float2(inv, __expf(m2 - m1) * inv);
    *(float2*)&oid[tk * 2] = make_float2((float)i1, (float)i2);
}

extern "C" void kernel_launch(void* const* d_in, const int* in_sizes, int n_in,
                              void* d_out, int out_size) {
    const float* x = (const float*)d_in[0];   // [8,4096,1024]
    const float* W = (const float*)d_in[1];   // [64,1024]
    const float* b = (const float*)d_in[2];   // [64]
    float* out = (float*)d_out;

    const int num_tokens = in_sizes[0] / K_DIM;   // 32768
    const int grid = 2 * HALF;                    // 296

    cudaFuncSetAttribute(router_mixed_kernel,
                         cudaFuncAttributeMaxDynamicSharedMemorySize, SMEM_FLOATS * 4);
    router_mixed_kernel<<<grid, 256, SMEM_FLOATS * 4>>>(x, W, b, out, num_tokens);
}